// round 2
// baseline (speedup 1.0000x reference)
#include <cuda_runtime.h>
#include <math.h>

#define Bn   8
#define Hn   56
#define Wn   56
#define Cn   192
#define NWIN 1568      // 8 * 14 * 14
#define IND  3072      // 4*4*192
#define HID  256
#define NCL  256
#define PIX  (Bn*Hn*Wn)   // 25088

#define OUT_ELEMS   (PIX*Cn)          // 4816896
#define CL_ELEMS    (NWIN*NCL)        // 401408
#define SUM_ELEMS   (NWIN)            // 1568
#define TOTAL_ELEMS (OUT_ELEMS + CL_ELEMS + SUM_ELEMS)

// ---------------- scratch (device globals: no allocation allowed) ----------
__device__ float    g_A[NWIN*IND];       // windowed LN features (19.3 MB)
__device__ float    g_tm[NWIN*HID];      // pre-sigmoid TM inputs
__device__ float    g_logits[NWIN*Cn];   // clause-vote logits
__device__ unsigned g_pos[NCL*8];        // include masks, direct literals
__device__ unsigned g_neg[NCL*8];        // include masks, negated literals
__device__ float    g_cl_fallback[NWIN*NCL];
__device__ float    g_sum_fallback[NWIN];

__device__ __forceinline__ float sigmoidf_(float x) { return 1.f / (1.f + expf(-x)); }

// ---------------- K1: LayerNorm + roll(-2,-2) + window partition ----------
__global__ __launch_bounds__(256) void ln_window_kernel(
    const float* __restrict__ x, const float* __restrict__ gamma,
    const float* __restrict__ beta)
{
    int warp = threadIdx.x >> 5;
    int lane = threadIdx.x & 31;
    int p = blockIdx.x * 8 + warp;          // destination pixel (post-roll frame)
    int b   = p / (Hn*Wn);
    int rem = p % (Hn*Wn);
    int h = rem / Wn, w = rem % Wn;
    int sh = (h + 2) % Hn, sw = (w + 2) % Wn;  // roll(-2): dst[h] = src[(h+2)%H]
    const float* src = x + ((size_t)(b*Hn + sh)*Wn + sw)*Cn;

    float v[6], s = 0.f, s2 = 0.f;
    #pragma unroll
    for (int k = 0; k < 6; k++) { v[k] = src[lane + 32*k]; s += v[k]; s2 += v[k]*v[k]; }
    #pragma unroll
    for (int o = 16; o > 0; o >>= 1) {
        s  += __shfl_xor_sync(0xffffffffu, s,  o);
        s2 += __shfl_xor_sync(0xffffffffu, s2, o);
    }
    float mean = s * (1.f/Cn);
    float var  = s2 * (1.f/Cn) - mean*mean;
    float inv  = rsqrtf(var + 1e-5f);

    int hb = h >> 2, i = h & 3, wb = w >> 2, j = w & 3;
    int row = (b*14 + hb)*14 + wb;
    float* dst = g_A + (size_t)row*IND + (i*4 + j)*Cn;
    #pragma unroll
    for (int k = 0; k < 6; k++) {
        int c = lane + 32*k;
        dst[c] = (v[k] - mean)*inv*gamma[c] + beta[c];
    }
}

// ---------------- K2: GEMM1  pre = A @ W1 + b1  (1568x3072 @ 3072x256) ----
__global__ __launch_bounds__(256) void gemm1_kernel(
    const float* __restrict__ W1, const float* __restrict__ b1)
{
    __shared__ float As[32][32];
    __shared__ float Bs[32][64];
    int tid  = threadIdx.x;
    int row0 = blockIdx.y * 32;
    int col0 = blockIdx.x * 64;
    int ar = tid >> 3, ac = (tid & 7) * 4;
    int br = tid >> 4, bc = (tid & 15) * 4;
    int tr = (tid >> 4) * 2, tc = (tid & 15) * 4;
    float acc[2][4] = {};

    for (int k0 = 0; k0 < IND; k0 += 32) {
        *(float4*)&As[ar][ac]      = *(const float4*)&g_A[(size_t)(row0+ar)*IND + k0 + ac];
        *(float4*)&Bs[br][bc]      = *(const float4*)&W1[(size_t)(k0+br)*HID + col0 + bc];
        *(float4*)&Bs[br+16][bc]   = *(const float4*)&W1[(size_t)(k0+br+16)*HID + col0 + bc];
        __syncthreads();
        #pragma unroll
        for (int kk = 0; kk < 32; kk++) {
            float a0 = As[tr][kk], a1 = As[tr+1][kk];
            float4 bv = *(float4*)&Bs[kk][tc];
            acc[0][0] += a0*bv.x; acc[0][1] += a0*bv.y; acc[0][2] += a0*bv.z; acc[0][3] += a0*bv.w;
            acc[1][0] += a1*bv.x; acc[1][1] += a1*bv.y; acc[1][2] += a1*bv.z; acc[1][3] += a1*bv.w;
        }
        __syncthreads();
    }
    #pragma unroll
    for (int m = 0; m < 2; m++)
        #pragma unroll
        for (int n = 0; n < 4; n++) {
            int col = col0 + tc + n;
            g_tm[(size_t)(row0+tr+m)*HID + col] = acc[m][n] + b1[col];
        }
}

// ---------------- K3: include masks from inc_w ----------------------------
__global__ __launch_bounds__(256) void inc_mask_kernel(const float* __restrict__ inc_w)
{
    int cl = blockIdx.x;
    int t  = threadIdx.x;                        // literal index within each half
    // sigmoid(w) > 0.5  <=>  w > 0
    unsigned pb = __ballot_sync(0xffffffffu, inc_w[(size_t)cl*512 + t]       > 0.f);
    unsigned nb = __ballot_sync(0xffffffffu, inc_w[(size_t)cl*512 + 256 + t] > 0.f);
    if ((t & 31) == 0) {
        g_pos[cl*8 + (t >> 5)] = pb;
        g_neg[cl*8 + (t >> 5)] = nb;
    }
}

// ---------------- K4: bits -> clauses -> summary -> logits ----------------
__global__ __launch_bounds__(256) void clause_kernel(
    const float* __restrict__ vote_w,
    float* __restrict__ clauses_out, float* __restrict__ summary_out)
{
    int row = blockIdx.x;
    int t   = threadIdx.x;
    __shared__ unsigned s_bits[8];
    __shared__ float    s_fire[NCL];
    __shared__ int      s_cnt[8];

    // fallback to device-global scratch when harness output has no room
    if (clauses_out == nullptr) clauses_out = g_cl_fallback;
    if (summary_out == nullptr) summary_out = g_sum_fallback;

    // feature bits: tm_in > 0.5  <=>  pre > 0
    float pre = g_tm[(size_t)row*HID + t];
    unsigned bb = __ballot_sync(0xffffffffu, pre > 0.f);
    if ((t & 31) == 0) s_bits[t >> 5] = bb;
    __syncthreads();

    unsigned bits[8];
    #pragma unroll
    for (int w = 0; w < 8; w++) bits[w] = s_bits[w];

    // clause t fires iff every included direct literal has bit=1 and every
    // included negated literal has bit=0
    uint4 p0 = *(const uint4*)&g_pos[t*8];
    uint4 p1 = *(const uint4*)&g_pos[t*8 + 4];
    uint4 n0 = *(const uint4*)&g_neg[t*8];
    uint4 n1 = *(const uint4*)&g_neg[t*8 + 4];
    unsigned viol = 0;
    viol |= (p0.x & ~bits[0]) | (n0.x & bits[0]);
    viol |= (p0.y & ~bits[1]) | (n0.y & bits[1]);
    viol |= (p0.z & ~bits[2]) | (n0.z & bits[2]);
    viol |= (p0.w & ~bits[3]) | (n0.w & bits[3]);
    viol |= (p1.x & ~bits[4]) | (n1.x & bits[4]);
    viol |= (p1.y & ~bits[5]) | (n1.y & bits[5]);
    viol |= (p1.z & ~bits[6]) | (n1.z & bits[6]);
    viol |= (p1.w & ~bits[7]) | (n1.w & bits[7]);
    bool fire = (viol == 0);

    clauses_out[(size_t)row*NCL + t] = fire ? 1.f : 0.f;
    s_fire[t] = fire ? 1.f : 0.f;
    unsigned fb = __ballot_sync(0xffffffffu, fire);
    if ((t & 31) == 0) s_cnt[t >> 5] = __popc(fb);
    __syncthreads();

    if (t == 0) {
        int tot = 0;
        #pragma unroll
        for (int w = 0; w < 8; w++) tot += s_cnt[w];
        summary_out[row] = tot * (1.f/256.f);
    }

    // logits[c] = sum_{firing cl} vote_w[cl,c] / sqrt(256)
    if (t < Cn) {
        float acc = 0.f;
        for (int cl = 0; cl < NCL; cl++) {
            if (s_fire[cl] != 0.f)                 // block-uniform branch
                acc += vote_w[(size_t)cl*Cn + t];
        }
        g_logits[(size_t)row*Cn + t] = acc * 0.0625f;
    }
}

// ---------------- K5: GEMM3 + sigmoid + gate blend + reverse/roll + res ---
__global__ __launch_bounds__(256) void gemm3_kernel(
    const float* __restrict__ x, const float* __restrict__ W2,
    const float* __restrict__ b2, const float* __restrict__ gate,
    float* __restrict__ out)
{
    __shared__ float As[32][32];
    __shared__ float Bs[32][64];
    int tid  = threadIdx.x;
    int row0 = blockIdx.y * 32;
    int col0 = blockIdx.x * 64;
    int ar = tid >> 3, ac = (tid & 7) * 4;
    int br = tid >> 4, bc = (tid & 15) * 4;
    int tr = (tid >> 4) * 2, tc = (tid & 15) * 4;
    float acc[2][4] = {};

    for (int k0 = 0; k0 < Cn; k0 += 32) {
        *(float4*)&As[ar][ac]    = *(const float4*)&g_logits[(size_t)(row0+ar)*Cn + k0 + ac];
        *(float4*)&Bs[br][bc]    = *(const float4*)&W2[(size_t)(k0+br)*IND + col0 + bc];
        *(float4*)&Bs[br+16][bc] = *(const float4*)&W2[(size_t)(k0+br+16)*IND + col0 + bc];
        __syncthreads();
        #pragma unroll
        for (int kk = 0; kk < 32; kk++) {
            float a0 = As[tr][kk], a1 = As[tr+1][kk];
            float4 bv = *(float4*)&Bs[kk][tc];
            acc[0][0] += a0*bv.x; acc[0][1] += a0*bv.y; acc[0][2] += a0*bv.z; acc[0][3] += a0*bv.w;
            acc[1][0] += a1*bv.x; acc[1][1] += a1*bv.y; acc[1][2] += a1*bv.z; acc[1][3] += a1*bv.w;
        }
        __syncthreads();
    }

    float gs = sigmoidf_(gate[0]);
    #pragma unroll
    for (int m = 0; m < 2; m++)
        #pragma unroll
        for (int n = 0; n < 4; n++) {
            int r   = row0 + tr + m;
            int col = col0 + tc + n;
            float mg = sigmoidf_(acc[m][n] + b2[col]);
            float fused = gs*mg + (1.f - gs)*sigmoidf_(mg);
            // window reverse + roll(+2,+2)
            int b  = r / 196, rr = r % 196;
            int hb = rr / 14, wb = rr % 14;
            int pp = col / Cn, c = col % Cn;
            int i = pp >> 2, j = pp & 3;
            int h = (hb*4 + i + 2) % Hn;
            int w = (wb*4 + j + 2) % Wn;
            size_t oi = ((size_t)(b*Hn + h)*Wn + w)*Cn + c;
            out[oi] = x[oi] + fused;   // residual is un-rolled original x
        }
}

// ---------------- launch ---------------------------------------------------
extern "C" void kernel_launch(void* const* d_in, const int* in_sizes, int n_in,
                              void* d_out, int out_size)
{
    const float* x      = (const float*)d_in[0];
    const float* gamma  = (const float*)d_in[1];
    const float* beta   = (const float*)d_in[2];
    const float* W1     = (const float*)d_in[3];
    const float* b1     = (const float*)d_in[4];
    const float* inc_w  = (const float*)d_in[5];
    const float* vote_w = (const float*)d_in[6];
    const float* W2     = (const float*)d_in[7];
    const float* b2     = (const float*)d_in[8];
    const float* gate   = (const float*)d_in[9];

    float* out = (float*)d_out;
    float* clauses_out = nullptr;   // nullptr -> kernel falls back to scratch
    float* summary_out = nullptr;
    if (out_size >= TOTAL_ELEMS) {
        clauses_out = out + OUT_ELEMS;
        summary_out = out + OUT_ELEMS + CL_ELEMS;
    }

    ln_window_kernel<<<PIX/8, 256>>>(x, gamma, beta);
    gemm1_kernel<<<dim3(HID/64, NWIN/32), 256>>>(W1, b1);
    inc_mask_kernel<<<NCL, 256>>>(inc_w);
    clause_kernel<<<NWIN, 256>>>(vote_w, clauses_out, summary_out);
    gemm3_kernel<<<dim3(IND/64, NWIN/32), 256>>>(x, W2, b2, gate, out);
}

// round 3
// speedup vs baseline: 2.5499x; 2.5499x over previous
#include <cuda_runtime.h>
#include <math.h>

#define Bn   8
#define Hn   56
#define Wn   56
#define Cn   192
#define NWIN 1568      // 8 * 14 * 14
#define IND  3072      // 4*4*192
#define HID  256
#define NCL  256
#define PIX  (Bn*Hn*Wn)   // 25088

#define OUT_ELEMS   (PIX*Cn)          // 4816896
#define CL_ELEMS    (NWIN*NCL)        // 401408
#define SUM_ELEMS   (NWIN)
#define TOTAL_ELEMS (OUT_ELEMS + CL_ELEMS + SUM_ELEMS)

// ---------------- scratch (device globals: no allocation allowed) ----------
__device__ float    g_A[NWIN*IND];       // windowed LN features
__device__ float    g_tm[NWIN*HID];      // pre-sigmoid TM inputs
__device__ float    g_logits[NWIN*Cn];   // clause-vote logits
__device__ unsigned g_pos[NCL*8];
__device__ unsigned g_neg[NCL*8];
__device__ float    g_cl_fallback[NWIN*NCL];
__device__ float    g_sum_fallback[NWIN];

__device__ __forceinline__ float sigmoidf_(float x) { return 1.f / (1.f + expf(-x)); }

__device__ __forceinline__ void mma_tf32(float* d,
    unsigned a0, unsigned a1, unsigned a2, unsigned a3,
    unsigned b0, unsigned b1)
{
    asm volatile(
        "mma.sync.aligned.m16n8k8.row.col.f32.tf32.tf32.f32 "
        "{%0,%1,%2,%3},{%4,%5,%6,%7},{%8,%9},{%0,%1,%2,%3};\n"
        : "+f"(d[0]), "+f"(d[1]), "+f"(d[2]), "+f"(d[3])
        : "r"(a0), "r"(a1), "r"(a2), "r"(a3), "r"(b0), "r"(b1));
}

// ---------------- K1: LayerNorm + roll(-2,-2) + window partition ----------
__global__ __launch_bounds__(256) void ln_window_kernel(
    const float* __restrict__ x, const float* __restrict__ gamma,
    const float* __restrict__ beta)
{
    int warp = threadIdx.x >> 5;
    int lane = threadIdx.x & 31;
    int p = blockIdx.x * 8 + warp;
    int b   = p / (Hn*Wn);
    int rem = p % (Hn*Wn);
    int h = rem / Wn, w = rem % Wn;
    int sh = (h + 2) % Hn, sw = (w + 2) % Wn;
    const float* src = x + ((size_t)(b*Hn + sh)*Wn + sw)*Cn;

    float v[6], s = 0.f, s2 = 0.f;
    #pragma unroll
    for (int k = 0; k < 6; k++) { v[k] = src[lane + 32*k]; s += v[k]; s2 += v[k]*v[k]; }
    #pragma unroll
    for (int o = 16; o > 0; o >>= 1) {
        s  += __shfl_xor_sync(0xffffffffu, s,  o);
        s2 += __shfl_xor_sync(0xffffffffu, s2, o);
    }
    float mean = s * (1.f/Cn);
    float var  = s2 * (1.f/Cn) - mean*mean;
    float inv  = rsqrtf(var + 1e-5f);

    int hb = h >> 2, i = h & 3, wb = w >> 2, j = w & 3;
    int row = (b*14 + hb)*14 + wb;
    float* dst = g_A + (size_t)row*IND + (i*4 + j)*Cn;
    #pragma unroll
    for (int k = 0; k < 6; k++) {
        int c = lane + 32*k;
        dst[c] = (v[k] - mean)*inv*gamma[c] + beta[c];
    }
}

// ---------------- K2: tensor-core GEMM1  g_tm = g_A @ W1 + b1 -------------
// M=1568 N=256 K=3072, CTA tile 64x64, 8 warps (2x4), warp tile 32x16
__global__ __launch_bounds__(256) void gemm1_tc(
    const float* __restrict__ W1, const float* __restrict__ b1)
{
    __shared__ float As[2][64*36];
    __shared__ float Bs[2][32*68];
    const int tid  = threadIdx.x;
    const int warp = tid >> 5, lane = tid & 31;
    const int gid = lane >> 2, tig = lane & 3;
    const int wm = warp >> 2, wn = warp & 3;      // 2 x 4 warp grid
    const int row0 = blockIdx.y * 64;
    const int col0 = blockIdx.x * 64;

    // load indices
    const int ar = tid >> 3, ac = (tid & 7) * 4;      // A: rows ar, ar+32
    const int brr = tid >> 4, bcc = (tid & 15) * 4;   // B: rows brr, brr+16
    int arow0 = row0 + ar;      if (arow0 > NWIN-1) arow0 = NWIN-1;
    int arow1 = row0 + ar + 32; if (arow1 > NWIN-1) arow1 = NWIN-1;

    float acc[2][2][4] = {};

    // preload chunk 0
    float4 na0 = *(const float4*)&g_A[(size_t)arow0*IND + ac];
    float4 na1 = *(const float4*)&g_A[(size_t)arow1*IND + ac];
    float4 nb0 = *(const float4*)&W1[(size_t)brr*HID + col0 + bcc];
    float4 nb1 = *(const float4*)&W1[(size_t)(brr+16)*HID + col0 + bcc];
    *(float4*)&As[0][ar*36 + ac] = na0;
    *(float4*)&As[0][(ar+32)*36 + ac] = na1;
    *(float4*)&Bs[0][brr*68 + bcc] = nb0;
    *(float4*)&Bs[0][(brr+16)*68 + bcc] = nb1;
    __syncthreads();

    const int NCHUNK = IND/32;   // 96
    for (int kc = 0; kc < NCHUNK; kc++) {
        int buf = kc & 1;
        if (kc + 1 < NCHUNK) {
            int k0 = (kc+1)*32;
            na0 = *(const float4*)&g_A[(size_t)arow0*IND + k0 + ac];
            na1 = *(const float4*)&g_A[(size_t)arow1*IND + k0 + ac];
            nb0 = *(const float4*)&W1[(size_t)(k0+brr)*HID + col0 + bcc];
            nb1 = *(const float4*)&W1[(size_t)(k0+brr+16)*HID + col0 + bcc];
        }
        const float* A_ = As[buf];
        const float* B_ = Bs[buf];
        #pragma unroll
        for (int ks = 0; ks < 4; ks++) {
            int k = ks*8;
            unsigned a[2][4], bfr[2][2];
            #pragma unroll
            for (int mt = 0; mt < 2; mt++) {
                int r = wm*32 + mt*16 + gid;
                a[mt][0] = __float_as_uint(A_[r*36 + k + tig]);
                a[mt][1] = __float_as_uint(A_[(r+8)*36 + k + tig]);
                a[mt][2] = __float_as_uint(A_[r*36 + k + tig + 4]);
                a[mt][3] = __float_as_uint(A_[(r+8)*36 + k + tig + 4]);
            }
            #pragma unroll
            for (int nt = 0; nt < 2; nt++) {
                int c = wn*16 + nt*8 + gid;
                bfr[nt][0] = __float_as_uint(B_[(k+tig)*68 + c]);
                bfr[nt][1] = __float_as_uint(B_[(k+tig+4)*68 + c]);
            }
            #pragma unroll
            for (int mt = 0; mt < 2; mt++)
                #pragma unroll
                for (int nt = 0; nt < 2; nt++)
                    mma_tf32(acc[mt][nt], a[mt][0], a[mt][1], a[mt][2], a[mt][3],
                             bfr[nt][0], bfr[nt][1]);
        }
        if (kc + 1 < NCHUNK) {
            int nb = buf ^ 1;
            *(float4*)&As[nb][ar*36 + ac] = na0;
            *(float4*)&As[nb][(ar+32)*36 + ac] = na1;
            *(float4*)&Bs[nb][brr*68 + bcc] = nb0;
            *(float4*)&Bs[nb][(brr+16)*68 + bcc] = nb1;
            __syncthreads();
        }
    }

    #pragma unroll
    for (int mt = 0; mt < 2; mt++)
        #pragma unroll
        for (int nt = 0; nt < 2; nt++)
            #pragma unroll
            for (int e = 0; e < 4; e++) {
                int r   = row0 + wm*32 + mt*16 + gid + (e >= 2 ? 8 : 0);
                int col = col0 + wn*16 + nt*8 + 2*tig + (e & 1);
                if (r < NWIN)
                    g_tm[(size_t)r*HID + col] = acc[mt][nt][e] + b1[col];
            }
}

// ---------------- K3: include masks ----------------------------------------
__global__ __launch_bounds__(256) void inc_mask_kernel(const float* __restrict__ inc_w)
{
    int cl = blockIdx.x;
    int t  = threadIdx.x;
    unsigned pb = __ballot_sync(0xffffffffu, inc_w[(size_t)cl*512 + t]       > 0.f);
    unsigned nb = __ballot_sync(0xffffffffu, inc_w[(size_t)cl*512 + 256 + t] > 0.f);
    if ((t & 31) == 0) {
        g_pos[cl*8 + (t >> 5)] = pb;
        g_neg[cl*8 + (t >> 5)] = nb;
    }
}

// ---------------- K4: clauses + summary + logits (8 rows per block) -------
__global__ __launch_bounds__(256) void clause8_kernel(
    const float* __restrict__ vote_w,
    float* __restrict__ clauses_out, float* __restrict__ summary_out)
{
    int t = threadIdx.x;
    int row0 = blockIdx.x * 8;
    __shared__ unsigned s_bits[8];
    __shared__ int      s_cnt[8];
    __shared__ int      s_nfire;
    __shared__ unsigned short s_list[NCL];

    if (clauses_out == nullptr) clauses_out = g_cl_fallback;
    if (summary_out == nullptr) summary_out = g_sum_fallback;

    // each thread owns clause t's masks for all 8 rows
    uint4 p0 = *(const uint4*)&g_pos[t*8];
    uint4 p1 = *(const uint4*)&g_pos[t*8 + 4];
    uint4 n0 = *(const uint4*)&g_neg[t*8];
    uint4 n1 = *(const uint4*)&g_neg[t*8 + 4];

    for (int r = 0; r < 8; r++) {
        int row = row0 + r;
        if (t == 0) s_nfire = 0;
        float pre = g_tm[(size_t)row*HID + t];
        unsigned bb = __ballot_sync(0xffffffffu, pre > 0.f);
        if ((t & 31) == 0) s_bits[t >> 5] = bb;
        __syncthreads();

        unsigned b0_ = s_bits[0], b1_ = s_bits[1], b2_ = s_bits[2], b3_ = s_bits[3];
        unsigned b4_ = s_bits[4], b5_ = s_bits[5], b6_ = s_bits[6], b7_ = s_bits[7];
        unsigned viol = 0;
        viol |= (p0.x & ~b0_) | (n0.x & b0_);
        viol |= (p0.y & ~b1_) | (n0.y & b1_);
        viol |= (p0.z & ~b2_) | (n0.z & b2_);
        viol |= (p0.w & ~b3_) | (n0.w & b3_);
        viol |= (p1.x & ~b4_) | (n1.x & b4_);
        viol |= (p1.y & ~b5_) | (n1.y & b5_);
        viol |= (p1.z & ~b6_) | (n1.z & b6_);
        viol |= (p1.w & ~b7_) | (n1.w & b7_);
        bool fire = (viol == 0);

        clauses_out[(size_t)row*NCL + t] = fire ? 1.f : 0.f;
        if (fire) { int idx = atomicAdd(&s_nfire, 1); s_list[idx] = (unsigned short)t; }
        unsigned fb = __ballot_sync(0xffffffffu, fire);
        if ((t & 31) == 0) s_cnt[t >> 5] = __popc(fb);
        __syncthreads();

        if (t == 0) {
            int tot = 0;
            #pragma unroll
            for (int w = 0; w < 8; w++) tot += s_cnt[w];
            summary_out[row] = tot * (1.f/256.f);
        }
        if (t < Cn) {
            float acc = 0.f;
            int nf = s_nfire;
            for (int i = 0; i < nf; i++)
                acc += vote_w[(size_t)s_list[i]*Cn + t];
            g_logits[(size_t)row*Cn + t] = acc * 0.0625f;
        }
        __syncthreads();
    }
}

// ---------------- K5: tensor-core GEMM3 + fused epilogue -------------------
// M=1568 N=3072 K=192, CTA tile 64x64
__global__ __launch_bounds__(256) void gemm3_tc(
    const float* __restrict__ x, const float* __restrict__ W2,
    const float* __restrict__ b2, const float* __restrict__ gate,
    float* __restrict__ out)
{
    __shared__ float As[2][64*36];
    __shared__ float Bs[2][32*68];
    const int tid  = threadIdx.x;
    const int warp = tid >> 5, lane = tid & 31;
    const int gid = lane >> 2, tig = lane & 3;
    const int wm = warp >> 2, wn = warp & 3;
    const int row0 = blockIdx.y * 64;
    const int col0 = blockIdx.x * 64;

    const int ar = tid >> 3, ac = (tid & 7) * 4;
    const int brr = tid >> 4, bcc = (tid & 15) * 4;
    int arow0 = row0 + ar;      if (arow0 > NWIN-1) arow0 = NWIN-1;
    int arow1 = row0 + ar + 32; if (arow1 > NWIN-1) arow1 = NWIN-1;

    float acc[2][2][4] = {};

    float4 na0 = *(const float4*)&g_logits[(size_t)arow0*Cn + ac];
    float4 na1 = *(const float4*)&g_logits[(size_t)arow1*Cn + ac];
    float4 nb0 = *(const float4*)&W2[(size_t)brr*IND + col0 + bcc];
    float4 nb1 = *(const float4*)&W2[(size_t)(brr+16)*IND + col0 + bcc];
    *(float4*)&As[0][ar*36 + ac] = na0;
    *(float4*)&As[0][(ar+32)*36 + ac] = na1;
    *(float4*)&Bs[0][brr*68 + bcc] = nb0;
    *(float4*)&Bs[0][(brr+16)*68 + bcc] = nb1;
    __syncthreads();

    const int NCHUNK = Cn/32;   // 6
    for (int kc = 0; kc < NCHUNK; kc++) {
        int buf = kc & 1;
        if (kc + 1 < NCHUNK) {
            int k0 = (kc+1)*32;
            na0 = *(const float4*)&g_logits[(size_t)arow0*Cn + k0 + ac];
            na1 = *(const float4*)&g_logits[(size_t)arow1*Cn + k0 + ac];
            nb0 = *(const float4*)&W2[(size_t)(k0+brr)*IND + col0 + bcc];
            nb1 = *(const float4*)&W2[(size_t)(k0+brr+16)*IND + col0 + bcc];
        }
        const float* A_ = As[buf];
        const float* B_ = Bs[buf];
        #pragma unroll
        for (int ks = 0; ks < 4; ks++) {
            int k = ks*8;
            unsigned a[2][4], bfr[2][2];
            #pragma unroll
            for (int mt = 0; mt < 2; mt++) {
                int r = wm*32 + mt*16 + gid;
                a[mt][0] = __float_as_uint(A_[r*36 + k + tig]);
                a[mt][1] = __float_as_uint(A_[(r+8)*36 + k + tig]);
                a[mt][2] = __float_as_uint(A_[r*36 + k + tig + 4]);
                a[mt][3] = __float_as_uint(A_[(r+8)*36 + k + tig + 4]);
            }
            #pragma unroll
            for (int nt = 0; nt < 2; nt++) {
                int c = wn*16 + nt*8 + gid;
                bfr[nt][0] = __float_as_uint(B_[(k+tig)*68 + c]);
                bfr[nt][1] = __float_as_uint(B_[(k+tig+4)*68 + c]);
            }
            #pragma unroll
            for (int mt = 0; mt < 2; mt++)
                #pragma unroll
                for (int nt = 0; nt < 2; nt++)
                    mma_tf32(acc[mt][nt], a[mt][0], a[mt][1], a[mt][2], a[mt][3],
                             bfr[nt][0], bfr[nt][1]);
        }
        if (kc + 1 < NCHUNK) {
            int nb = buf ^ 1;
            *(float4*)&As[nb][ar*36 + ac] = na0;
            *(float4*)&As[nb][(ar+32)*36 + ac] = na1;
            *(float4*)&Bs[nb][brr*68 + bcc] = nb0;
            *(float4*)&Bs[nb][(brr+16)*68 + bcc] = nb1;
            __syncthreads();
        }
    }

    float gs = sigmoidf_(gate[0]);
    #pragma unroll
    for (int mt = 0; mt < 2; mt++)
        #pragma unroll
        for (int nt = 0; nt < 2; nt++)
            #pragma unroll
            for (int e = 0; e < 4; e++) {
                int r   = row0 + wm*32 + mt*16 + gid + (e >= 2 ? 8 : 0);
                int col = col0 + wn*16 + nt*8 + 2*tig + (e & 1);
                if (r >= NWIN) continue;
                float mg = sigmoidf_(acc[mt][nt][e] + b2[col]);
                float fused = gs*mg + (1.f - gs)*sigmoidf_(mg);
                int b  = r / 196, rr = r % 196;
                int hb = rr / 14, wb = rr % 14;
                int pp = col / Cn, c = col % Cn;
                int i = pp >> 2, j = pp & 3;
                int h = (hb*4 + i + 2) % Hn;
                int w = (wb*4 + j + 2) % Wn;
                size_t oi = ((size_t)(b*Hn + h)*Wn + w)*Cn + c;
                out[oi] = x[oi] + fused;
            }
}

// ---------------- launch ---------------------------------------------------
extern "C" void kernel_launch(void* const* d_in, const int* in_sizes, int n_in,
                              void* d_out, int out_size)
{
    const float* x      = (const float*)d_in[0];
    const float* gamma  = (const float*)d_in[1];
    const float* beta   = (const float*)d_in[2];
    const float* W1     = (const float*)d_in[3];
    const float* b1     = (const float*)d_in[4];
    const float* inc_w  = (const float*)d_in[5];
    const float* vote_w = (const float*)d_in[6];
    const float* W2     = (const float*)d_in[7];
    const float* b2     = (const float*)d_in[8];
    const float* gate   = (const float*)d_in[9];

    float* out = (float*)d_out;
    float* clauses_out = nullptr;
    float* summary_out = nullptr;
    if (out_size >= TOTAL_ELEMS) {
        clauses_out = out + OUT_ELEMS;
        summary_out = out + OUT_ELEMS + CL_ELEMS;
    }

    ln_window_kernel<<<PIX/8, 256>>>(x, gamma, beta);
    gemm1_tc<<<dim3(HID/64, (NWIN+63)/64), 256>>>(W1, b1);
    inc_mask_kernel<<<NCL, 256>>>(inc_w);
    clause8_kernel<<<NWIN/8, 256>>>(vote_w, clauses_out, summary_out);
    gemm3_tc<<<dim3(IND/64, (NWIN+63)/64), 256>>>(x, W2, b2, gate, out);
}

// round 9
// speedup vs baseline: 2.7053x; 1.0609x over previous
#include <cuda_runtime.h>
#include <math.h>

#define Bn   8
#define Hn   56
#define Wn   56
#define Cn   192
#define NWIN 1568      // 8 * 14 * 14
#define IND  3072      // 4*4*192
#define HID  256
#define NCL  256
#define PIX  (Bn*Hn*Wn)   // 25088

#define OUT_ELEMS   (PIX*Cn)          // 4816896
#define CL_ELEMS    (NWIN*NCL)        // 401408
#define SUM_ELEMS   (NWIN)
#define TOTAL_ELEMS (OUT_ELEMS + CL_ELEMS + SUM_ELEMS)

// ---------------- scratch (device globals: no allocation allowed) ----------
__device__ float    g_A[NWIN*IND];        // windowed LN features
__device__ float    g_tmp[2][NWIN*HID];   // split-K partials of GEMM1
__device__ unsigned g_bits[NWIN*8];       // per-window feature bitsets
__device__ float    g_logits[NWIN*Cn];    // clause-vote logits
__device__ unsigned g_pos[NCL*8];
__device__ unsigned g_neg[NCL*8];
__device__ float    g_cl_fallback[NWIN*NCL];
__device__ float    g_sum_fallback[NWIN];

__device__ __forceinline__ float sigmoidf_(float x) { return 1.f / (1.f + expf(-x)); }

__device__ __forceinline__ void mma_tf32(float* d,
    unsigned a0, unsigned a1, unsigned a2, unsigned a3,
    unsigned b0, unsigned b1)
{
    asm volatile(
        "mma.sync.aligned.m16n8k8.row.col.f32.tf32.tf32.f32 "
        "{%0,%1,%2,%3},{%4,%5,%6,%7},{%8,%9},{%0,%1,%2,%3};\n"
        : "+f"(d[0]), "+f"(d[1]), "+f"(d[2]), "+f"(d[3])
        : "r"(a0), "r"(a1), "r"(a2), "r"(a3), "r"(b0), "r"(b1));
}

// ---------------- K1: LayerNorm + roll(-2,-2) + window partition ----------
__global__ __launch_bounds__(256) void ln_window_kernel(
    const float* __restrict__ x, const float* __restrict__ gamma,
    const float* __restrict__ beta)
{
    int warp = threadIdx.x >> 5;
    int lane = threadIdx.x & 31;
    int p = blockIdx.x * 8 + warp;
    int b   = p / (Hn*Wn);
    int rem = p % (Hn*Wn);
    int h = rem / Wn, w = rem % Wn;
    int sh = (h + 2) % Hn, sw = (w + 2) % Wn;
    const float* src = x + ((size_t)(b*Hn + sh)*Wn + sw)*Cn;

    float v[6], s = 0.f, s2 = 0.f;
    #pragma unroll
    for (int k = 0; k < 6; k++) { v[k] = src[lane + 32*k]; s += v[k]; s2 += v[k]*v[k]; }
    #pragma unroll
    for (int o = 16; o > 0; o >>= 1) {
        s  += __shfl_xor_sync(0xffffffffu, s,  o);
        s2 += __shfl_xor_sync(0xffffffffu, s2, o);
    }
    float mean = s * (1.f/Cn);
    float var  = s2 * (1.f/Cn) - mean*mean;
    float inv  = rsqrtf(var + 1e-5f);

    int hb = h >> 2, i = h & 3, wb = w >> 2, j = w & 3;
    int row = (b*14 + hb)*14 + wb;
    float* dst = g_A + (size_t)row*IND + (i*4 + j)*Cn;
    #pragma unroll
    for (int k = 0; k < 6; k++) {
        int c = lane + 32*k;
        dst[c] = (v[k] - mean)*inv*gamma[c] + beta[c];
    }
}

// ---------------- K2: tensor-core GEMM1 split-K  g_tmp[z] = A@W1 partial --
// M=1568 N=256 K=1536 per z, CTA tile 64x64, 8 warps (2x4)
__global__ __launch_bounds__(256) void gemm1_tc(const float* __restrict__ W1)
{
    __shared__ float As[2][64*36];
    __shared__ float Bs[2][32*68];
    const int tid  = threadIdx.x;
    const int warp = tid >> 5, lane = tid & 31;
    const int gid = lane >> 2, tig = lane & 3;
    const int wm = warp >> 2, wn = warp & 3;
    const int row0 = blockIdx.y * 64;
    const int col0 = blockIdx.x * 64;
    const int kz   = blockIdx.z;
    const int kbase = kz * (IND/2);

    const int ar = tid >> 3, ac = (tid & 7) * 4;
    const int brr = tid >> 4, bcc = (tid & 15) * 4;
    int arow0 = row0 + ar;      if (arow0 > NWIN-1) arow0 = NWIN-1;
    int arow1 = row0 + ar + 32; if (arow1 > NWIN-1) arow1 = NWIN-1;

    float acc[2][2][4] = {};

    float4 na0 = *(const float4*)&g_A[(size_t)arow0*IND + kbase + ac];
    float4 na1 = *(const float4*)&g_A[(size_t)arow1*IND + kbase + ac];
    float4 nb0 = *(const float4*)&W1[(size_t)(kbase+brr)*HID + col0 + bcc];
    float4 nb1 = *(const float4*)&W1[(size_t)(kbase+brr+16)*HID + col0 + bcc];
    *(float4*)&As[0][ar*36 + ac] = na0;
    *(float4*)&As[0][(ar+32)*36 + ac] = na1;
    *(float4*)&Bs[0][brr*68 + bcc] = nb0;
    *(float4*)&Bs[0][(brr+16)*68 + bcc] = nb1;
    __syncthreads();

    const int NCHUNK = (IND/2)/32;   // 48
    for (int kc = 0; kc < NCHUNK; kc++) {
        int buf = kc & 1;
        if (kc + 1 < NCHUNK) {
            int k0 = kbase + (kc+1)*32;
            na0 = *(const float4*)&g_A[(size_t)arow0*IND + k0 + ac];
            na1 = *(const float4*)&g_A[(size_t)arow1*IND + k0 + ac];
            nb0 = *(const float4*)&W1[(size_t)(k0+brr)*HID + col0 + bcc];
            nb1 = *(const float4*)&W1[(size_t)(k0+brr+16)*HID + col0 + bcc];
        }
        const float* A_ = As[buf];
        const float* B_ = Bs[buf];
        #pragma unroll
        for (int ks = 0; ks < 4; ks++) {
            int k = ks*8;
            unsigned a[2][4], bfr[2][2];
            #pragma unroll
            for (int mt = 0; mt < 2; mt++) {
                int r = wm*32 + mt*16 + gid;
                a[mt][0] = __float_as_uint(A_[r*36 + k + tig]);
                a[mt][1] = __float_as_uint(A_[(r+8)*36 + k + tig]);
                a[mt][2] = __float_as_uint(A_[r*36 + k + tig + 4]);
                a[mt][3] = __float_as_uint(A_[(r+8)*36 + k + tig + 4]);
            }
            #pragma unroll
            for (int nt = 0; nt < 2; nt++) {
                int c = wn*16 + nt*8 + gid;
                bfr[nt][0] = __float_as_uint(B_[(k+tig)*68 + c]);
                bfr[nt][1] = __float_as_uint(B_[(k+tig+4)*68 + c]);
            }
            #pragma unroll
            for (int mt = 0; mt < 2; mt++)
                #pragma unroll
                for (int nt = 0; nt < 2; nt++)
                    mma_tf32(acc[mt][nt], a[mt][0], a[mt][1], a[mt][2], a[mt][3],
                             bfr[nt][0], bfr[nt][1]);
        }
        if (kc + 1 < NCHUNK) {
            int nb = buf ^ 1;
            *(float4*)&As[nb][ar*36 + ac] = na0;
            *(float4*)&As[nb][(ar+32)*36 + ac] = na1;
            *(float4*)&Bs[nb][brr*68 + bcc] = nb0;
            *(float4*)&Bs[nb][(brr+16)*68 + bcc] = nb1;
            __syncthreads();
        }
    }

    float* dst = g_tmp[kz];
    #pragma unroll
    for (int mt = 0; mt < 2; mt++)
        #pragma unroll
        for (int nt = 0; nt < 2; nt++)
            #pragma unroll
            for (int e = 0; e < 4; e++) {
                int r   = row0 + wm*32 + mt*16 + gid + (e >= 2 ? 8 : 0);
                int col = col0 + wn*16 + nt*8 + 2*tig + (e & 1);
                if (r < NWIN)
                    dst[(size_t)r*HID + col] = acc[mt][nt][e];
            }
}

// ---------------- K2b: reduce partials + b1 -> feature bits ----------------
__global__ __launch_bounds__(256) void reduce_bits_kernel(const float* __restrict__ b1)
{
    int row = blockIdx.x;
    int t   = threadIdx.x;
    size_t i = (size_t)row*HID + t;
    float pre = g_tmp[0][i] + g_tmp[1][i] + b1[t];
    unsigned bb = __ballot_sync(0xffffffffu, pre > 0.f);
    if ((t & 31) == 0) g_bits[row*8 + (t >> 5)] = bb;
}

// ---------------- K3: include masks ----------------------------------------
__global__ __launch_bounds__(256) void inc_mask_kernel(const float* __restrict__ inc_w)
{
    int cl = blockIdx.x;
    int t  = threadIdx.x;
    unsigned pb = __ballot_sync(0xffffffffu, inc_w[(size_t)cl*512 + t]       > 0.f);
    unsigned nb = __ballot_sync(0xffffffffu, inc_w[(size_t)cl*512 + 256 + t] > 0.f);
    if ((t & 31) == 0) {
        g_pos[cl*8 + (t >> 5)] = pb;
        g_neg[cl*8 + (t >> 5)] = nb;
    }
}

// ---------------- K4: clauses + summary + logits (8 rows, 2 syncs) --------
__global__ __launch_bounds__(256) void clause8_kernel(
    const float* __restrict__ vote_w,
    float* __restrict__ clauses_out, float* __restrict__ summary_out)
{
    int t = threadIdx.x;
    int row0 = blockIdx.x * 8;
    __shared__ unsigned s_bits[8][8];
    __shared__ int      s_nfire[8];
    __shared__ int      s_tot[8];
    __shared__ unsigned short s_list[8][NCL];

    if (clauses_out == nullptr) clauses_out = g_cl_fallback;
    if (summary_out == nullptr) summary_out = g_sum_fallback;

    if (t < 64) ((unsigned*)s_bits)[t] = g_bits[row0*8 + t];
    if (t < 8) { s_nfire[t] = 0; s_tot[t] = 0; }
    __syncthreads();

    // thread t owns clause t; masks in registers for all 8 rows
    uint4 p0 = *(const uint4*)&g_pos[t*8];
    uint4 p1 = *(const uint4*)&g_pos[t*8 + 4];
    uint4 n0 = *(const uint4*)&g_neg[t*8];
    uint4 n1 = *(const uint4*)&g_neg[t*8 + 4];

    #pragma unroll
    for (int r = 0; r < 8; r++) {
        unsigned b0_ = s_bits[r][0], b1_ = s_bits[r][1], b2_ = s_bits[r][2], b3_ = s_bits[r][3];
        unsigned b4_ = s_bits[r][4], b5_ = s_bits[r][5], b6_ = s_bits[r][6], b7_ = s_bits[r][7];
        unsigned viol = 0;
        viol |= (p0.x & ~b0_) | (n0.x & b0_);
        viol |= (p0.y & ~b1_) | (n0.y & b1_);
        viol |= (p0.z & ~b2_) | (n0.z & b2_);
        viol |= (p0.w & ~b3_) | (n0.w & b3_);
        viol |= (p1.x & ~b4_) | (n1.x & b4_);
        viol |= (p1.y & ~b5_) | (n1.y & b5_);
        viol |= (p1.z & ~b6_) | (n1.z & b6_);
        viol |= (p1.w & ~b7_) | (n1.w & b7_);
        bool fire = (viol == 0);

        clauses_out[(size_t)(row0 + r)*NCL + t] = fire ? 1.f : 0.f;
        unsigned fb = __ballot_sync(0xffffffffu, fire);
        if ((t & 31) == 0 && fb) atomicAdd(&s_tot[r], __popc(fb));
        if (fire) { int idx = atomicAdd(&s_nfire[r], 1); s_list[r][idx] = (unsigned short)t; }
    }
    __syncthreads();

    if (t < 8) summary_out[row0 + t] = s_tot[t] * (1.f/256.f);

    if (t < Cn) {
        #pragma unroll
        for (int r = 0; r < 8; r++) {
            float acc = 0.f;
            int nf = s_nfire[r];
            for (int i = 0; i < nf; i++)
                acc += vote_w[(size_t)s_list[r][i]*Cn + t];
            g_logits[(size_t)(row0 + r)*Cn + t] = acc * 0.0625f;
        }
    }
}

// ---------------- K5: tensor-core GEMM3 + fused epilogue -------------------
// M=1568 N=3072 K=192, CTA tile 64x64
__global__ __launch_bounds__(256) void gemm3_tc(
    const float* __restrict__ x, const float* __restrict__ W2,
    const float* __restrict__ b2, const float* __restrict__ gate,
    float* __restrict__ out)
{
    __shared__ float As[2][64*36];
    __shared__ float Bs[2][32*68];
    const int tid  = threadIdx.x;
    const int warp = tid >> 5, lane = tid & 31;
    const int gid = lane >> 2, tig = lane & 3;
    const int wm = warp >> 2, wn = warp & 3;
    const int row0 = blockIdx.y * 64;
    const int col0 = blockIdx.x * 64;

    const int ar = tid >> 3, ac = (tid & 7) * 4;
    const int brr = tid >> 4, bcc = (tid & 15) * 4;
    int arow0 = row0 + ar;      if (arow0 > NWIN-1) arow0 = NWIN-1;
    int arow1 = row0 + ar + 32; if (arow1 > NWIN-1) arow1 = NWIN-1;

    float acc[2][2][4] = {};

    float4 na0 = *(const float4*)&g_logits[(size_t)arow0*Cn + ac];
    float4 na1 = *(const float4*)&g_logits[(size_t)arow1*Cn + ac];
    float4 nb0 = *(const float4*)&W2[(size_t)brr*IND + col0 + bcc];
    float4 nb1 = *(const float4*)&W2[(size_t)(brr+16)*IND + col0 + bcc];
    *(float4*)&As[0][ar*36 + ac] = na0;
    *(float4*)&As[0][(ar+32)*36 + ac] = na1;
    *(float4*)&Bs[0][brr*68 + bcc] = nb0;
    *(float4*)&Bs[0][(brr+16)*68 + bcc] = nb1;
    __syncthreads();

    const int NCHUNK = Cn/32;   // 6
    for (int kc = 0; kc < NCHUNK; kc++) {
        int buf = kc & 1;
        if (kc + 1 < NCHUNK) {
            int k0 = (kc+1)*32;
            na0 = *(const float4*)&g_logits[(size_t)arow0*Cn + k0 + ac];
            na1 = *(const float4*)&g_logits[(size_t)arow1*Cn + k0 + ac];
            nb0 = *(const float4*)&W2[(size_t)(k0+brr)*IND + col0 + bcc];
            nb1 = *(const float4*)&W2[(size_t)(k0+brr+16)*IND + col0 + bcc];
        }
        const float* A_ = As[buf];
        const float* B_ = Bs[buf];
        #pragma unroll
        for (int ks = 0; ks < 4; ks++) {
            int k = ks*8;
            unsigned a[2][4], bfr[2][2];
            #pragma unroll
            for (int mt = 0; mt < 2; mt++) {
                int r = wm*32 + mt*16 + gid;
                a[mt][0] = __float_as_uint(A_[r*36 + k + tig]);
                a[mt][1] = __float_as_uint(A_[(r+8)*36 + k + tig]);
                a[mt][2] = __float_as_uint(A_[r*36 + k + tig + 4]);
                a[mt][3] = __float_as_uint(A_[(r+8)*36 + k + tig + 4]);
            }
            #pragma unroll
            for (int nt = 0; nt < 2; nt++) {
                int c = wn*16 + nt*8 + gid;
                bfr[nt][0] = __float_as_uint(B_[(k+tig)*68 + c]);
                bfr[nt][1] = __float_as_uint(B_[(k+tig+4)*68 + c]);
            }
            #pragma unroll
            for (int mt = 0; mt < 2; mt++)
                #pragma unroll
                for (int nt = 0; nt < 2; nt++)
                    mma_tf32(acc[mt][nt], a[mt][0], a[mt][1], a[mt][2], a[mt][3],
                             bfr[nt][0], bfr[nt][1]);
        }
        if (kc + 1 < NCHUNK) {
            int nb = buf ^ 1;
            *(float4*)&As[nb][ar*36 + ac] = na0;
            *(float4*)&As[nb][(ar+32)*36 + ac] = na1;
            *(float4*)&Bs[nb][brr*68 + bcc] = nb0;
            *(float4*)&Bs[nb][(brr+16)*68 + bcc] = nb1;
            __syncthreads();
        }
    }

    float gs = sigmoidf_(gate[0]);
    #pragma unroll
    for (int mt = 0; mt < 2; mt++)
        #pragma unroll
        for (int nt = 0; nt < 2; nt++)
            #pragma unroll
            for (int e = 0; e < 4; e++) {
                int r   = row0 + wm*32 + mt*16 + gid + (e >= 2 ? 8 : 0);
                int col = col0 + wn*16 + nt*8 + 2*tig + (e & 1);
                if (r >= NWIN) continue;
                float mg = sigmoidf_(acc[mt][nt][e] + b2[col]);
                float fused = gs*mg + (1.f - gs)*sigmoidf_(mg);
                int b  = r / 196, rr = r % 196;
                int hb = rr / 14, wb = rr % 14;
                int pp = col / Cn, c = col % Cn;
                int i = pp >> 2, j = pp & 3;
                int h = (hb*4 + i + 2) % Hn;
                int w = (wb*4 + j + 2) % Wn;
                size_t oi = ((size_t)(b*Hn + h)*Wn + w)*Cn + c;
                out[oi] = x[oi] + fused;
            }
}

// ---------------- launch ---------------------------------------------------
extern "C" void kernel_launch(void* const* d_in, const int* in_sizes, int n_in,
                              void* d_out, int out_size)
{
    const float* x      = (const float*)d_in[0];
    const float* gamma  = (const float*)d_in[1];
    const float* beta   = (const float*)d_in[2];
    const float* W1     = (const float*)d_in[3];
    const float* b1     = (const float*)d_in[4];
    const float* inc_w  = (const float*)d_in[5];
    const float* vote_w = (const float*)d_in[6];
    const float* W2     = (const float*)d_in[7];
    const float* b2     = (const float*)d_in[8];
    const float* gate   = (const float*)d_in[9];

    float* out = (float*)d_out;
    float* clauses_out = nullptr;
    float* summary_out = nullptr;
    if (out_size >= TOTAL_ELEMS) {
        clauses_out = out + OUT_ELEMS;
        summary_out = out + OUT_ELEMS + CL_ELEMS;
    }

    ln_window_kernel<<<PIX/8, 256>>>(x, gamma, beta);
    gemm1_tc<<<dim3(HID/64, (NWIN+63)/64, 2), 256>>>(W1);
    reduce_bits_kernel<<<NWIN, 256>>>(b1);
    inc_mask_kernel<<<NCL, 256>>>(inc_w);
    clause8_kernel<<<NWIN/8, 256>>>(vote_w, clauses_out, summary_out);
    gemm3_tc<<<dim3(IND/64, (NWIN+63)/64), 256>>>(x, W2, b2, gate, out);
}

// round 10
// speedup vs baseline: 4.1173x; 1.5220x over previous
#include <cuda_runtime.h>
#include <cuda_bf16.h>
#include <math.h>

#define Bn   8
#define Hn   56
#define Wn   56
#define Cn   192
#define NWIN 1568      // 8 * 14 * 14
#define IND  3072      // 4*4*192
#define HID  256
#define NCL  256
#define PIX  (Bn*Hn*Wn)   // 25088

#define OUT_ELEMS   (PIX*Cn)
#define CL_ELEMS    (NWIN*NCL)
#define SUM_ELEMS   (NWIN)
#define TOTAL_ELEMS (OUT_ELEMS + CL_ELEMS + SUM_ELEMS)

#define LN_BLOCKS   (PIX/8)          // 3136

// ---------------- scratch ---------------------------------------------------
__device__ __nv_bfloat16 g_A[NWIN*IND];      // windowed LN features (bf16)
__device__ __nv_bfloat16 g_W1t[HID*IND];     // W1 transposed [n][k] bf16
__device__ __nv_bfloat16 g_W2t[IND*Cn];      // W2 transposed [n][k] bf16
__device__ float         g_tmp[2][NWIN*HID]; // split-K partials of GEMM1
__device__ __nv_bfloat16 g_logB[NWIN*Cn];    // logits bf16
__device__ unsigned      g_pos[NCL*8];
__device__ unsigned      g_neg[NCL*8];
__device__ float         g_cl_fallback[NWIN*NCL];
__device__ float         g_sum_fallback[NWIN];

__device__ __forceinline__ float sigmoidf_(float x) { return 1.f / (1.f + expf(-x)); }

__device__ __forceinline__ void mma_bf16(float* d,
    unsigned a0, unsigned a1, unsigned a2, unsigned a3,
    unsigned b0, unsigned b1)
{
    asm volatile(
        "mma.sync.aligned.m16n8k16.row.col.f32.bf16.bf16.f32 "
        "{%0,%1,%2,%3},{%4,%5,%6,%7},{%8,%9},{%0,%1,%2,%3};\n"
        : "+f"(d[0]), "+f"(d[1]), "+f"(d[2]), "+f"(d[3])
        : "r"(a0), "r"(a1), "r"(a2), "r"(a3), "r"(b0), "r"(b1));
}

// ---------------- K1: LN + roll + window partition  (+ inc masks) ----------
__global__ __launch_bounds__(256) void fused_pre_kernel(
    const float* __restrict__ x, const float* __restrict__ gamma,
    const float* __restrict__ beta, const float* __restrict__ inc_w)
{
    if (blockIdx.x >= LN_BLOCKS) {
        // include-mask part: one block per clause
        int cl = blockIdx.x - LN_BLOCKS;
        int t  = threadIdx.x;
        unsigned pb = __ballot_sync(0xffffffffu, inc_w[(size_t)cl*512 + t]       > 0.f);
        unsigned nb = __ballot_sync(0xffffffffu, inc_w[(size_t)cl*512 + 256 + t] > 0.f);
        if ((t & 31) == 0) {
            g_pos[cl*8 + (t >> 5)] = pb;
            g_neg[cl*8 + (t >> 5)] = nb;
        }
        return;
    }
    int warp = threadIdx.x >> 5;
    int lane = threadIdx.x & 31;
    int p = blockIdx.x * 8 + warp;
    int b   = p / (Hn*Wn);
    int rem = p % (Hn*Wn);
    int h = rem / Wn, w = rem % Wn;
    int sh = (h + 2) % Hn, sw = (w + 2) % Wn;
    const float* src = x + ((size_t)(b*Hn + sh)*Wn + sw)*Cn;

    float v[6], s = 0.f, s2 = 0.f;
    #pragma unroll
    for (int k = 0; k < 6; k++) { v[k] = src[lane + 32*k]; s += v[k]; s2 += v[k]*v[k]; }
    #pragma unroll
    for (int o = 16; o > 0; o >>= 1) {
        s  += __shfl_xor_sync(0xffffffffu, s,  o);
        s2 += __shfl_xor_sync(0xffffffffu, s2, o);
    }
    float mean = s * (1.f/Cn);
    float var  = s2 * (1.f/Cn) - mean*mean;
    float inv  = rsqrtf(var + 1e-5f);

    int hb = h >> 2, i = h & 3, wb = w >> 2, j = w & 3;
    int row = (b*14 + hb)*14 + wb;
    __nv_bfloat16* dst = g_A + (size_t)row*IND + (i*4 + j)*Cn;
    #pragma unroll
    for (int k = 0; k < 6; k++) {
        int c = lane + 32*k;
        dst[c] = __float2bfloat16((v[k] - mean)*inv*gamma[c] + beta[c]);
    }
}

// ---------------- K2: convert + transpose weights to bf16 ------------------
// W1 [3072][256] -> g_W1t [256][3072];  W2 [192][3072] -> g_W2t [3072][192]
#define W1_TILES (96*8)     // 768
#define W2_TILES (6*96)     // 576
__global__ __launch_bounds__(256) void convert_w_kernel(
    const float* __restrict__ W1, const float* __restrict__ W2)
{
    __shared__ float tile[32][33];
    int tx = threadIdx.x & 31, ty = threadIdx.x >> 5;
    int q = blockIdx.x;
    if (q < W1_TILES) {
        int bi = q >> 3, bj = q & 7;
        int r0 = bi*32, c0 = bj*32;
        #pragma unroll
        for (int i = 0; i < 4; i++)
            tile[ty + 8*i][tx] = W1[(size_t)(r0 + ty + 8*i)*HID + c0 + tx];
        __syncthreads();
        #pragma unroll
        for (int i = 0; i < 4; i++)
            g_W1t[(size_t)(c0 + ty + 8*i)*IND + r0 + tx] =
                __float2bfloat16(tile[tx][ty + 8*i]);
    } else {
        q -= W1_TILES;
        int bi = q / 96, bj = q % 96;
        int r0 = bi*32, c0 = bj*32;
        #pragma unroll
        for (int i = 0; i < 4; i++)
            tile[ty + 8*i][tx] = W2[(size_t)(r0 + ty + 8*i)*IND + c0 + tx];
        __syncthreads();
        #pragma unroll
        for (int i = 0; i < 4; i++)
            g_W2t[(size_t)(c0 + ty + 8*i)*Cn + r0 + tx] =
                __float2bfloat16(tile[tx][ty + 8*i]);
    }
}

// ---------------- K3: bf16 GEMM1 split-K  g_tmp[z] = A@W1 partial ----------
// M=1568 N=256 K=1536 per z; CTA 64x64; K-chunk 64; 8 warps (2x4), warp 32x16
__global__ __launch_bounds__(256) void gemm1_tc()
{
    __shared__ __nv_bfloat16 As[2][64*72];
    __shared__ __nv_bfloat16 Bs[2][64*72];
    const int tid  = threadIdx.x;
    const int warp = tid >> 5, lane = tid & 31;
    const int gid = lane >> 2, tig = lane & 3;
    const int wm = warp >> 2, wn = warp & 3;
    const int row0 = blockIdx.y * 64;
    const int col0 = blockIdx.x * 64;
    const int kbase = blockIdx.z * (IND/2);

    // load slots: s = tid, tid+256 ; r = s>>3 (0..63), c8 = (s&7)*8
    int r0s = tid >> 3,        c80 = (tid & 7) * 8;
    int r1s = (tid+256) >> 3,  c81 = (tid & 7) * 8;
    int arow0 = row0 + r0s; if (arow0 > NWIN-1) arow0 = NWIN-1;
    int arow1 = row0 + r1s; if (arow1 > NWIN-1) arow1 = NWIN-1;

    float acc[2][2][4] = {};

    uint4 na0 = *(const uint4*)(g_A + (size_t)arow0*IND + kbase + c80);
    uint4 na1 = *(const uint4*)(g_A + (size_t)arow1*IND + kbase + c81);
    uint4 nb0 = *(const uint4*)(g_W1t + (size_t)(col0 + r0s)*IND + kbase + c80);
    uint4 nb1 = *(const uint4*)(g_W1t + (size_t)(col0 + r1s)*IND + kbase + c81);
    *(uint4*)&As[0][r0s*72 + c80] = na0;
    *(uint4*)&As[0][r1s*72 + c81] = na1;
    *(uint4*)&Bs[0][r0s*72 + c80] = nb0;
    *(uint4*)&Bs[0][r1s*72 + c81] = nb1;
    __syncthreads();

    const int NCHUNK = (IND/2)/64;   // 24
    for (int kc = 0; kc < NCHUNK; kc++) {
        int buf = kc & 1;
        if (kc + 1 < NCHUNK) {
            int koff = kbase + (kc+1)*64;
            na0 = *(const uint4*)(g_A + (size_t)arow0*IND + koff + c80);
            na1 = *(const uint4*)(g_A + (size_t)arow1*IND + koff + c81);
            nb0 = *(const uint4*)(g_W1t + (size_t)(col0 + r0s)*IND + koff + c80);
            nb1 = *(const uint4*)(g_W1t + (size_t)(col0 + r1s)*IND + koff + c81);
        }
        const unsigned* Aw = (const unsigned*)As[buf];
        const unsigned* Bw = (const unsigned*)Bs[buf];
        #pragma unroll
        for (int ks = 0; ks < 4; ks++) {
            int kw = ks*8;   // word offset (16 bf16 per step = 8 words)
            unsigned a[2][4], bfr[2][2];
            #pragma unroll
            for (int mt = 0; mt < 2; mt++) {
                int r = wm*32 + mt*16 + gid;
                int base = r*36 + kw + tig;
                a[mt][0] = Aw[base];
                a[mt][1] = Aw[base + 288];       // row +8
                a[mt][2] = Aw[base + 4];         // col +8 bf16
                a[mt][3] = Aw[base + 292];
            }
            #pragma unroll
            for (int nt = 0; nt < 2; nt++) {
                int n = wn*16 + nt*8 + gid;
                int bb = n*36 + kw + tig;
                bfr[nt][0] = Bw[bb];
                bfr[nt][1] = Bw[bb + 4];
            }
            #pragma unroll
            for (int mt = 0; mt < 2; mt++)
                #pragma unroll
                for (int nt = 0; nt < 2; nt++)
                    mma_bf16(acc[mt][nt], a[mt][0], a[mt][1], a[mt][2], a[mt][3],
                             bfr[nt][0], bfr[nt][1]);
        }
        if (kc + 1 < NCHUNK) {
            int nb = buf ^ 1;
            *(uint4*)&As[nb][r0s*72 + c80] = na0;
            *(uint4*)&As[nb][r1s*72 + c81] = na1;
            *(uint4*)&Bs[nb][r0s*72 + c80] = nb0;
            *(uint4*)&Bs[nb][r1s*72 + c81] = nb1;
            __syncthreads();
        }
    }

    float* dst = g_tmp[blockIdx.z];
    #pragma unroll
    for (int mt = 0; mt < 2; mt++)
        #pragma unroll
        for (int nt = 0; nt < 2; nt++)
            #pragma unroll
            for (int e = 0; e < 4; e++) {
                int r   = row0 + wm*32 + mt*16 + gid + (e >= 2 ? 8 : 0);
                int col = col0 + wn*16 + nt*8 + 2*tig + (e & 1);
                if (r < NWIN)
                    dst[(size_t)r*HID + col] = acc[mt][nt][e];
            }
}

// ---------------- K4: bits + clauses + summary + logits --------------------
__global__ __launch_bounds__(256) void clause8_kernel(
    const float* __restrict__ b1, const float* __restrict__ vote_w,
    float* __restrict__ clauses_out, float* __restrict__ summary_out)
{
    int t = threadIdx.x;
    int row0 = blockIdx.x * 8;
    __shared__ unsigned s_bits[8][8];
    __shared__ int      s_nfire[8];
    __shared__ int      s_tot[8];
    __shared__ unsigned short s_list[8][NCL];

    if (clauses_out == nullptr) clauses_out = g_cl_fallback;
    if (summary_out == nullptr) summary_out = g_sum_fallback;

    if (t < 8) { s_nfire[t] = 0; s_tot[t] = 0; }
    // feature bits from split-K partials + bias (fused reduce)
    float bias = b1[t];
    #pragma unroll
    for (int r = 0; r < 8; r++) {
        size_t i = (size_t)(row0 + r)*HID + t;
        float pre = g_tmp[0][i] + g_tmp[1][i] + bias;
        unsigned bb = __ballot_sync(0xffffffffu, pre > 0.f);
        if ((t & 31) == 0) s_bits[r][t >> 5] = bb;
    }
    __syncthreads();

    uint4 p0 = *(const uint4*)&g_pos[t*8];
    uint4 p1 = *(const uint4*)&g_pos[t*8 + 4];
    uint4 n0 = *(const uint4*)&g_neg[t*8];
    uint4 n1 = *(const uint4*)&g_neg[t*8 + 4];

    #pragma unroll
    for (int r = 0; r < 8; r++) {
        unsigned b0_ = s_bits[r][0], b1_ = s_bits[r][1], b2_ = s_bits[r][2], b3_ = s_bits[r][3];
        unsigned b4_ = s_bits[r][4], b5_ = s_bits[r][5], b6_ = s_bits[r][6], b7_ = s_bits[r][7];
        unsigned viol = 0;
        viol |= (p0.x & ~b0_) | (n0.x & b0_);
        viol |= (p0.y & ~b1_) | (n0.y & b1_);
        viol |= (p0.z & ~b2_) | (n0.z & b2_);
        viol |= (p0.w & ~b3_) | (n0.w & b3_);
        viol |= (p1.x & ~b4_) | (n1.x & b4_);
        viol |= (p1.y & ~b5_) | (n1.y & b5_);
        viol |= (p1.z & ~b6_) | (n1.z & b6_);
        viol |= (p1.w & ~b7_) | (n1.w & b7_);
        bool fire = (viol == 0);

        clauses_out[(size_t)(row0 + r)*NCL + t] = fire ? 1.f : 0.f;
        unsigned fb = __ballot_sync(0xffffffffu, fire);
        if ((t & 31) == 0 && fb) atomicAdd(&s_tot[r], __popc(fb));
        if (fire) { int idx = atomicAdd(&s_nfire[r], 1); s_list[r][idx] = (unsigned short)t; }
    }
    __syncthreads();

    if (t < 8) summary_out[row0 + t] = s_tot[t] * (1.f/256.f);

    if (t < Cn) {
        #pragma unroll
        for (int r = 0; r < 8; r++) {
            float acc = 0.f;
            int nf = s_nfire[r];
            for (int i = 0; i < nf; i++)
                acc += vote_w[(size_t)s_list[r][i]*Cn + t];
            g_logB[(size_t)(row0 + r)*Cn + t] = __float2bfloat16(acc * 0.0625f);
        }
    }
}

// ---------------- K5: bf16 GEMM3 + fused epilogue --------------------------
// M=1568 N=3072 K=192; CTA 64x64; K-chunk 64 (3 chunks)
__global__ __launch_bounds__(256) void gemm3_tc(
    const float* __restrict__ x, const float* __restrict__ b2,
    const float* __restrict__ gate, float* __restrict__ out)
{
    __shared__ __nv_bfloat16 As[2][64*72];
    __shared__ __nv_bfloat16 Bs[2][64*72];
    const int tid  = threadIdx.x;
    const int warp = tid >> 5, lane = tid & 31;
    const int gid = lane >> 2, tig = lane & 3;
    const int wm = warp >> 2, wn = warp & 3;
    const int row0 = blockIdx.y * 64;
    const int col0 = blockIdx.x * 64;

    int r0s = tid >> 3,        c80 = (tid & 7) * 8;
    int r1s = (tid+256) >> 3,  c81 = (tid & 7) * 8;
    int arow0 = row0 + r0s; if (arow0 > NWIN-1) arow0 = NWIN-1;
    int arow1 = row0 + r1s; if (arow1 > NWIN-1) arow1 = NWIN-1;

    float acc[2][2][4] = {};

    uint4 na0 = *(const uint4*)(g_logB + (size_t)arow0*Cn + c80);
    uint4 na1 = *(const uint4*)(g_logB + (size_t)arow1*Cn + c81);
    uint4 nb0 = *(const uint4*)(g_W2t + (size_t)(col0 + r0s)*Cn + c80);
    uint4 nb1 = *(const uint4*)(g_W2t + (size_t)(col0 + r1s)*Cn + c81);
    *(uint4*)&As[0][r0s*72 + c80] = na0;
    *(uint4*)&As[0][r1s*72 + c81] = na1;
    *(uint4*)&Bs[0][r0s*72 + c80] = nb0;
    *(uint4*)&Bs[0][r1s*72 + c81] = nb1;
    __syncthreads();

    const int NCHUNK = Cn/64;   // 3
    for (int kc = 0; kc < NCHUNK; kc++) {
        int buf = kc & 1;
        if (kc + 1 < NCHUNK) {
            int koff = (kc+1)*64;
            na0 = *(const uint4*)(g_logB + (size_t)arow0*Cn + koff + c80);
            na1 = *(const uint4*)(g_logB + (size_t)arow1*Cn + koff + c81);
            nb0 = *(const uint4*)(g_W2t + (size_t)(col0 + r0s)*Cn + koff + c80);
            nb1 = *(const uint4*)(g_W2t + (size_t)(col0 + r1s)*Cn + koff + c81);
        }
        const unsigned* Aw = (const unsigned*)As[buf];
        const unsigned* Bw = (const unsigned*)Bs[buf];
        #pragma unroll
        for (int ks = 0; ks < 4; ks++) {
            int kw = ks*8;
            unsigned a[2][4], bfr[2][2];
            #pragma unroll
            for (int mt = 0; mt < 2; mt++) {
                int r = wm*32 + mt*16 + gid;
                int base = r*36 + kw + tig;
                a[mt][0] = Aw[base];
                a[mt][1] = Aw[base + 288];
                a[mt][2] = Aw[base + 4];
                a[mt][3] = Aw[base + 292];
            }
            #pragma unroll
            for (int nt = 0; nt < 2; nt++) {
                int n = wn*16 + nt*8 + gid;
                int bb = n*36 + kw + tig;
                bfr[nt][0] = Bw[bb];
                bfr[nt][1] = Bw[bb + 4];
            }
            #pragma unroll
            for (int mt = 0; mt < 2; mt++)
                #pragma unroll
                for (int nt = 0; nt < 2; nt++)
                    mma_bf16(acc[mt][nt], a[mt][0], a[mt][1], a[mt][2], a[mt][3],
                             bfr[nt][0], bfr[nt][1]);
        }
        if (kc + 1 < NCHUNK) {
            int nb = buf ^ 1;
            *(uint4*)&As[nb][r0s*72 + c80] = na0;
            *(uint4*)&As[nb][r1s*72 + c81] = na1;
            *(uint4*)&Bs[nb][r0s*72 + c80] = nb0;
            *(uint4*)&Bs[nb][r1s*72 + c81] = nb1;
            __syncthreads();
        }
    }

    float gs = sigmoidf_(gate[0]);
    #pragma unroll
    for (int mt = 0; mt < 2; mt++)
        #pragma unroll
        for (int nt = 0; nt < 2; nt++)
            #pragma unroll
            for (int e = 0; e < 4; e++) {
                int r   = row0 + wm*32 + mt*16 + gid + (e >= 2 ? 8 : 0);
                int col = col0 + wn*16 + nt*8 + 2*tig + (e & 1);
                if (r >= NWIN) continue;
                float mg = sigmoidf_(acc[mt][nt][e] + b2[col]);
                float fused = gs*mg + (1.f - gs)*sigmoidf_(mg);
                int b  = r / 196, rr = r % 196;
                int hb = rr / 14, wb = rr % 14;
                int pp = col / Cn, c = col % Cn;
                int i = pp >> 2, j = pp & 3;
                int h = (hb*4 + i + 2) % Hn;
                int w = (wb*4 + j + 2) % Wn;
                size_t oi = ((size_t)(b*Hn + h)*Wn + w)*Cn + c;
                out[oi] = x[oi] + fused;
            }
}

// ---------------- launch ---------------------------------------------------
extern "C" void kernel_launch(void* const* d_in, const int* in_sizes, int n_in,
                              void* d_out, int out_size)
{
    const float* x      = (const float*)d_in[0];
    const float* gamma  = (const float*)d_in[1];
    const float* beta   = (const float*)d_in[2];
    const float* W1     = (const float*)d_in[3];
    const float* b1     = (const float*)d_in[4];
    const float* inc_w  = (const float*)d_in[5];
    const float* vote_w = (const float*)d_in[6];
    const float* W2     = (const float*)d_in[7];
    const float* b2     = (const float*)d_in[8];
    const float* gate   = (const float*)d_in[9];

    float* out = (float*)d_out;
    float* clauses_out = nullptr;
    float* summary_out = nullptr;
    if (out_size >= TOTAL_ELEMS) {
        clauses_out = out + OUT_ELEMS;
        summary_out = out + OUT_ELEMS + CL_ELEMS;
    }

    fused_pre_kernel<<<LN_BLOCKS + NCL, 256>>>(x, gamma, beta, inc_w);
    convert_w_kernel<<<W1_TILES + W2_TILES, 256>>>(W1, W2);
    gemm1_tc<<<dim3(HID/64, (NWIN+63)/64, 2), 256>>>();
    clause8_kernel<<<NWIN/8, 256>>>(b1, vote_w, clauses_out, summary_out);
    gemm3_tc<<<dim3(IND/64, (NWIN+63)/64), 256>>>(x, b2, gate, out);
}